// round 1
// baseline (speedup 1.0000x reference)
#include <cuda_runtime.h>

#define NN 50000
#define NE 100000
#define NODE_IN 64
#define EDGE_IN 16
#define H 32
#define EH 128
#define NTN 343
#define NTE 21
#define STEPS 6

// ---------------- device scratch (no allocations allowed) ----------------
__device__ float d_h[NN * H];          // current hidden/h
__device__ float d_agg[NN * H];        // aggregated messages
__device__ float d_Wtab[NTE * H * H];  // per-type edge weight matrices
__device__ float d_htab[NTN * H];      // per-type projected node feats
__device__ int d_ssrc[NE];             // type-sorted edges
__device__ int d_sdst[NE];
__device__ int d_stype[NE];
__device__ int d_cnt[NTE];
__device__ int d_cur[NTE];

// ---------------- small helpers ----------------
__device__ __forceinline__ unsigned long long pk(float a, float b) {
    unsigned long long r;
    asm("mov.b64 %0, {%1, %2};" : "=l"(r) : "f"(a), "f"(b));
    return r;
}
__device__ __forceinline__ float2 upk(unsigned long long v) {
    float2 f;
    asm("mov.b64 {%0, %1}, %2;" : "=f"(f.x), "=f"(f.y) : "l"(v));
    return f;
}
// packed fp32x2 FMA (full-rate fp32 on sm_103a; plain FFMA-3reg is half rate)
__device__ __forceinline__ void ffma2(unsigned long long& acc,
                                      unsigned long long a,
                                      unsigned long long b) {
    asm("fma.rn.f32x2 %0, %1, %2, %0;" : "+l"(acc) : "l"(a), "l"(b));
}
__device__ __forceinline__ float sigm(float x) {
    return 1.0f / (1.0f + __expf(-x));
}
__device__ __forceinline__ float tanh_fast(float x) {
    // robust at large |x|: exp overflow -> 1, exp underflow -> -1
    float e = __expf(2.0f * x);
    return 1.0f - 2.0f / (e + 1.0f);
}

// ---------------- setup kernels ----------------
__global__ void k_zero_cnt() {
    int t = threadIdx.x;
    if (t < NTE) d_cnt[t] = 0;
}

__global__ void k_count(const int* __restrict__ eid) {
    int e = blockIdx.x * blockDim.x + threadIdx.x;
    if (e < NE) atomicAdd(&d_cnt[eid[e]], 1);
}

__global__ void k_scan() {
    int run = 0;
    for (int t = 0; t < NTE; t++) {
        d_cur[t] = run;
        run += d_cnt[t];
    }
}

__global__ void k_scatter(const int* __restrict__ eid,
                          const int* __restrict__ src,
                          const int* __restrict__ dst) {
    int e = blockIdx.x * blockDim.x + threadIdx.x;
    if (e < NE) {
        int t = eid[e];
        int p = atomicAdd(&d_cur[t], 1);
        d_ssrc[p] = src[e];
        d_sdst[p] = dst[e];
        d_stype[p] = t;
    }
}

// node projection table: h_tab[r] = relu(node_emb[r] @ proj_W + proj_b)
__global__ void k_htab(const float* __restrict__ node_emb,
                       const float* __restrict__ proj_W,
                       const float* __restrict__ proj_b) {
    int r = blockIdx.x;   // 0..342
    int o = threadIdx.x;  // 0..31
    float acc = proj_b[o];
    for (int i = 0; i < NODE_IN; i++)
        acc = fmaf(node_emb[r * NODE_IN + i], proj_W[i * H + o], acc);
    d_htab[r * H + o] = fmaxf(acc, 0.0f);
}

// edge weight table: W_tab[t] = (relu(edge_emb[t]@eW1+eb1) @ eW2 + eb2)
__global__ void k_wtab(const float* __restrict__ edge_emb,
                       const float* __restrict__ eW1,
                       const float* __restrict__ eb1,
                       const float* __restrict__ eW2,
                       const float* __restrict__ eb2) {
    __shared__ float sh[EH];
    int t = blockIdx.x;   // 0..20
    int k = threadIdx.x;  // 0..127
    float a = eb1[k];
    for (int i = 0; i < EDGE_IN; i++)
        a = fmaf(edge_emb[t * EDGE_IN + i], eW1[i * EH + k], a);
    sh[k] = fmaxf(a, 0.0f);
    __syncthreads();
    for (int c = 0; c < 8; c++) {
        int o = c * EH + k;  // coalesced
        float acc = eb2[o];
        for (int i = 0; i < EH; i++)
            acc = fmaf(sh[i], eW2[i * (H * H) + o], acc);
        d_Wtab[t * (H * H) + o] = acc;
    }
}

// initialize h from table, zero agg
__global__ void k_init(const int* __restrict__ node_ids) {
    int idx = blockIdx.x * blockDim.x + threadIdx.x;
    if (idx < NN * H) {
        int n = idx >> 5, o = idx & 31;
        d_h[idx] = d_htab[node_ids[n] * H + o];
        d_agg[idx] = 0.0f;
    }
}

// ---------------- message kernel ----------------
// Warps own a contiguous chunk of type-sorted edges; W held in registers
// (one column per lane). Per edge: coalesced h gather, 32 shfl broadcasts,
// 32 FFMA, coalesced 32-lane atomicAdd scatter.
#define MSG_BLOCKS 296
#define MSG_THREADS 256
#define MSG_WARPS (MSG_BLOCKS * (MSG_THREADS / 32))
#define MSG_CHUNK ((NE + MSG_WARPS - 1) / MSG_WARPS)

__global__ void k_message() {
    int gw = (blockIdx.x * blockDim.x + threadIdx.x) >> 5;
    int lane = threadIdx.x & 31;
    int p0 = gw * MSG_CHUNK;
    int p1 = min(NE, p0 + MSG_CHUNK);
    if (p0 >= p1) return;

    int cur_t = d_stype[p0];
    float w[H];
#pragma unroll
    for (int i = 0; i < H; i++) w[i] = d_Wtab[cur_t * (H * H) + i * H + lane];

    for (int p = p0; p < p1; p++) {
        int t = d_stype[p];
        if (t != cur_t) {
            cur_t = t;
#pragma unroll
            for (int i = 0; i < H; i++)
                w[i] = d_Wtab[cur_t * (H * H) + i * H + lane];
        }
        int s = d_ssrc[p];
        int d = d_sdst[p];
        float hv = d_h[s * H + lane];
        float a0 = 0.f, a1 = 0.f, a2 = 0.f, a3 = 0.f;
#pragma unroll
        for (int i = 0; i < H; i += 4) {
            a0 = fmaf(__shfl_sync(0xffffffffu, hv, i + 0), w[i + 0], a0);
            a1 = fmaf(__shfl_sync(0xffffffffu, hv, i + 1), w[i + 1], a1);
            a2 = fmaf(__shfl_sync(0xffffffffu, hv, i + 2), w[i + 2], a2);
            a3 = fmaf(__shfl_sync(0xffffffffu, hv, i + 3), w[i + 3], a3);
        }
        atomicAdd(&d_agg[d * H + lane], (a0 + a1) + (a2 + a3));
    }
}

// ---------------- GRU kernel ----------------
// Thread-per-node. m,h packed into f32x2 pairs; weights broadcast from
// shared via 128-bit loads; packed fma.rn.f32x2 for full-rate fp32.
// Also zeroes agg for the next step, and writes d_out on the final step.
__global__ void k_gru(const float* __restrict__ gWih,
                      const float* __restrict__ gWhh,
                      const float* __restrict__ gbih,
                      const float* __restrict__ gbhh,
                      const float* __restrict__ cb,
                      float* __restrict__ outp) {
    __shared__ __align__(16) float sWih[3 * H * H];
    __shared__ __align__(16) float sWhh[3 * H * H];
    __shared__ float sbih[3 * H], sbhh[3 * H], scb[H];

    for (int i = threadIdx.x; i < 3 * H * H; i += blockDim.x) {
        sWih[i] = gWih[i];
        sWhh[i] = gWhh[i];
    }
    for (int i = threadIdx.x; i < 3 * H; i += blockDim.x) {
        sbih[i] = gbih[i];
        sbhh[i] = gbhh[i];
    }
    if (threadIdx.x < H) scb[threadIdx.x] = cb[threadIdx.x];
    __syncthreads();

    int n = blockIdx.x * blockDim.x + threadIdx.x;
    if (n >= NN) return;

    unsigned long long m2[H / 2], h2[H / 2];
    {
        const float4* ag4 = (const float4*)(d_agg + (size_t)n * H);
        float4* agw = (float4*)(d_agg + (size_t)n * H);
        const float4* hh4 = (const float4*)(d_h + (size_t)n * H);
        float4 z4 = make_float4(0.f, 0.f, 0.f, 0.f);
#pragma unroll
        for (int q = 0; q < H / 4; q++) {
            float4 a = ag4[q];
            float b0 = fmaxf(a.x + scb[q * 4 + 0], 0.f);
            float b1 = fmaxf(a.y + scb[q * 4 + 1], 0.f);
            float b2 = fmaxf(a.z + scb[q * 4 + 2], 0.f);
            float b3 = fmaxf(a.w + scb[q * 4 + 3], 0.f);
            m2[2 * q + 0] = pk(b0, b1);
            m2[2 * q + 1] = pk(b2, b3);
            agw[q] = z4;  // reset agg for the next message pass
            float4 hh = hh4[q];
            h2[2 * q + 0] = pk(hh.x, hh.y);
            h2[2 * q + 1] = pk(hh.z, hh.w);
        }
    }

#pragma unroll 1
    for (int o = 0; o < H; o++) {
        const ulonglong2* Wr = (const ulonglong2*)(sWih + o * H);
        const ulonglong2* Wz = (const ulonglong2*)(sWih + (H + o) * H);
        const ulonglong2* Wn = (const ulonglong2*)(sWih + (2 * H + o) * H);
        const ulonglong2* Vr = (const ulonglong2*)(sWhh + o * H);
        const ulonglong2* Vz = (const ulonglong2*)(sWhh + (H + o) * H);
        const ulonglong2* Vn = (const ulonglong2*)(sWhh + (2 * H + o) * H);
        unsigned long long air = 0, aiz = 0, ain = 0, ahr = 0, ahz = 0, ahn = 0;
#pragma unroll
        for (int p = 0; p < H / 4; p++) {
            ulonglong2 w;
            w = Wr[p]; ffma2(air, m2[2 * p], w.x); ffma2(air, m2[2 * p + 1], w.y);
            w = Wz[p]; ffma2(aiz, m2[2 * p], w.x); ffma2(aiz, m2[2 * p + 1], w.y);
            w = Wn[p]; ffma2(ain, m2[2 * p], w.x); ffma2(ain, m2[2 * p + 1], w.y);
            w = Vr[p]; ffma2(ahr, h2[2 * p], w.x); ffma2(ahr, h2[2 * p + 1], w.y);
            w = Vz[p]; ffma2(ahz, h2[2 * p], w.x); ffma2(ahz, h2[2 * p + 1], w.y);
            w = Vn[p]; ffma2(ahn, h2[2 * p], w.x); ffma2(ahn, h2[2 * p + 1], w.y);
        }
        float2 f;
        f = upk(air); float ir = f.x + f.y + sbih[o];
        f = upk(aiz); float iz = f.x + f.y + sbih[H + o];
        f = upk(ain); float in_ = f.x + f.y + sbih[2 * H + o];
        f = upk(ahr); float hr = f.x + f.y + sbhh[o];
        f = upk(ahz); float hz = f.x + f.y + sbhh[H + o];
        f = upk(ahn); float hn = f.x + f.y + sbhh[2 * H + o];

        float r = sigm(ir + hr);
        float z = sigm(iz + hz);
        float nn = tanh_fast(in_ + r * hn);
        float2 hp = upk(h2[o >> 1]);
        float hdo = (o & 1) ? hp.y : hp.x;
        float hnew = (1.0f - z) * nn + z * hdo;
        d_h[(size_t)n * H + o] = hnew;
        if (outp) outp[(size_t)n * H + o] = hnew;
    }
}

// ---------------- launch ----------------
extern "C" void kernel_launch(void* const* d_in, const int* in_sizes, int n_in,
                              void* d_out, int out_size) {
    const int* node_ids = (const int*)d_in[0];
    const int* edge_ids = (const int*)d_in[1];
    const int* src = (const int*)d_in[2];
    const int* dst = (const int*)d_in[3];
    const float* node_emb = (const float*)d_in[4];
    const float* edge_emb = (const float*)d_in[5];
    const float* proj_W = (const float*)d_in[6];
    const float* proj_b = (const float*)d_in[7];
    const float* eW1 = (const float*)d_in[8];
    const float* eb1 = (const float*)d_in[9];
    const float* eW2 = (const float*)d_in[10];
    const float* eb2 = (const float*)d_in[11];
    const float* conv_bias = (const float*)d_in[12];
    const float* gWih = (const float*)d_in[13];
    const float* gWhh = (const float*)d_in[14];
    const float* gbih = (const float*)d_in[15];
    const float* gbhh = (const float*)d_in[16];
    float* out = (float*)d_out;

    // --- one-time (per call) precompute ---
    k_zero_cnt<<<1, 32>>>();
    k_count<<<(NE + 255) / 256, 256>>>(edge_ids);
    k_scan<<<1, 1>>>();
    k_scatter<<<(NE + 255) / 256, 256>>>(edge_ids, src, dst);
    k_htab<<<NTN, H>>>(node_emb, proj_W, proj_b);
    k_wtab<<<NTE, EH>>>(edge_emb, eW1, eb1, eW2, eb2);
    k_init<<<(NN * H + 255) / 256, 256>>>(node_ids);

    // --- 6 message-passing steps ---
    for (int s = 0; s < STEPS; s++) {
        k_message<<<MSG_BLOCKS, MSG_THREADS>>>();
        float* op = (s == STEPS - 1) ? out : nullptr;
        k_gru<<<(NN + 255) / 256, 256>>>(gWih, gWhh, gbih, gbhh, conv_bias, op);
    }
}

// round 2
// speedup vs baseline: 1.1553x; 1.1553x over previous
#include <cuda_runtime.h>

#define NN 50000
#define NE 100000
#define NODE_IN 64
#define EDGE_IN 16
#define H 32
#define EH 128
#define NTN 343
#define NTE 21
#define STEPS 6

// ---------------- device scratch (no allocations allowed) ----------------
__device__ float d_h[NN * H];          // current hidden/h
__device__ float d_agg[NN * H];        // aggregated messages
__device__ float d_Wtab[NTE * H * H];  // per-type edge weight matrices
__device__ float d_htab[NTN * H];      // per-type projected node feats
__device__ int d_ssrc[NE];             // type-sorted edges
__device__ int d_sdst[NE];
__device__ int d_stype[NE];
__device__ int d_cnt[NTE];
__device__ int d_cur[NTE];

// ---------------- small helpers ----------------
__device__ __forceinline__ unsigned long long pk(float a, float b) {
    unsigned long long r;
    asm("mov.b64 %0, {%1, %2};" : "=l"(r) : "f"(a), "f"(b));
    return r;
}
__device__ __forceinline__ float2 upk(unsigned long long v) {
    float2 f;
    asm("mov.b64 {%0, %1}, %2;" : "=f"(f.x), "=f"(f.y) : "l"(v));
    return f;
}
__device__ __forceinline__ void ffma2(unsigned long long& acc,
                                      unsigned long long a,
                                      unsigned long long b) {
    asm("fma.rn.f32x2 %0, %1, %2, %0;" : "+l"(acc) : "l"(a), "l"(b));
}
__device__ __forceinline__ float sigm(float x) {
    return 1.0f / (1.0f + __expf(-x));
}
__device__ __forceinline__ float tanh_fast(float x) {
    float e = __expf(2.0f * x);
    return 1.0f - 2.0f / (e + 1.0f);
}

// ---------------- setup kernels ----------------
__global__ void k_zero_cnt() {
    int t = threadIdx.x;
    if (t < NTE) { d_cnt[t] = 0; }
}

// block-aggregated histogram: 21 global atomics per BLOCK, not per thread
__global__ void k_count(const int* __restrict__ eid) {
    __shared__ int hc[NTE];
    if (threadIdx.x < NTE) hc[threadIdx.x] = 0;
    __syncthreads();
    int e = blockIdx.x * blockDim.x + threadIdx.x;
    if (e < NE) atomicAdd(&hc[eid[e]], 1);
    __syncthreads();
    if (threadIdx.x < NTE && hc[threadIdx.x])
        atomicAdd(&d_cnt[threadIdx.x], hc[threadIdx.x]);
}

__global__ void k_scan() {
    int run = 0;
    for (int t = 0; t < NTE; t++) {
        d_cur[t] = run;
        run += d_cnt[t];
    }
}

// block-aggregated scatter: local rank via smem atomics, one global
// atomic per type per block for the base offset
__global__ void k_scatter(const int* __restrict__ eid,
                          const int* __restrict__ src,
                          const int* __restrict__ dst) {
    __shared__ int hc[NTE];
    __shared__ int hbase[NTE];
    if (threadIdx.x < NTE) hc[threadIdx.x] = 0;
    __syncthreads();
    int e = blockIdx.x * blockDim.x + threadIdx.x;
    int t = 0, loc = 0;
    bool valid = (e < NE);
    if (valid) {
        t = eid[e];
        loc = atomicAdd(&hc[t], 1);
    }
    __syncthreads();
    if (threadIdx.x < NTE && hc[threadIdx.x])
        hbase[threadIdx.x] = atomicAdd(&d_cur[threadIdx.x], hc[threadIdx.x]);
    __syncthreads();
    if (valid) {
        int p = hbase[t] + loc;
        d_ssrc[p] = src[e];
        d_sdst[p] = dst[e];
        d_stype[p] = t;
    }
}

// node projection table
__global__ void k_htab(const float* __restrict__ node_emb,
                       const float* __restrict__ proj_W,
                       const float* __restrict__ proj_b) {
    int r = blockIdx.x;
    int o = threadIdx.x;
    float acc = proj_b[o];
    for (int i = 0; i < NODE_IN; i++)
        acc = fmaf(node_emb[r * NODE_IN + i], proj_W[i * H + o], acc);
    d_htab[r * H + o] = fmaxf(acc, 0.0f);
}

// edge weight table; grid = (21, 8): blockIdx.y picks the output chunk
__global__ void k_wtab(const float* __restrict__ edge_emb,
                       const float* __restrict__ eW1,
                       const float* __restrict__ eb1,
                       const float* __restrict__ eW2,
                       const float* __restrict__ eb2) {
    __shared__ float sh[EH];
    int t = blockIdx.x;
    int c = blockIdx.y;
    int k = threadIdx.x;
    float a = eb1[k];
#pragma unroll
    for (int i = 0; i < EDGE_IN; i++)
        a = fmaf(edge_emb[t * EDGE_IN + i], eW1[i * EH + k], a);
    sh[k] = fmaxf(a, 0.0f);
    __syncthreads();
    int o = c * EH + k;
    float acc = eb2[o];
#pragma unroll 8
    for (int i = 0; i < EH; i++)
        acc = fmaf(sh[i], eW2[i * (H * H) + o], acc);
    d_Wtab[t * (H * H) + o] = acc;
}

__global__ void k_init(const int* __restrict__ node_ids) {
    int idx = blockIdx.x * blockDim.x + threadIdx.x;
    if (idx < NN * H) {
        int n = idx >> 5, o = idx & 31;
        d_h[idx] = d_htab[node_ids[n] * H + o];
        d_agg[idx] = 0.0f;
    }
}

// ---------------- message kernel ----------------
// One warp per 32 type-sorted edges. Edge meta loaded lane-parallel
// (3 coalesced LDG per warp), broadcast via shfl. h[src] gather for
// edge j+1 prefetched while computing edge j. W cached in registers
// (one column per lane), reloaded only on (rare) type boundary.
#define MSG_TPB 256
#define MSG_NWARPS ((NE + 31) / 32)
#define MSG_BLOCKS ((MSG_NWARPS + (MSG_TPB / 32) - 1) / (MSG_TPB / 32))

__global__ void __launch_bounds__(MSG_TPB) k_message() {
    int gw = (blockIdx.x * MSG_TPB + threadIdx.x) >> 5;
    int lane = threadIdx.x & 31;
    int base = gw * 32;
    if (base >= NE) return;
    int nb = min(32, NE - base);

    int s = 0, d = 0, t = 0;
    if (lane < nb) {
        int e = base + lane;
        s = __ldg(&d_ssrc[e]);
        d = __ldg(&d_sdst[e]);
        t = __ldg(&d_stype[e]);
    }

    int cur_t = __shfl_sync(0xffffffffu, t, 0);
    float w[H];
#pragma unroll
    for (int i = 0; i < H; i++)
        w[i] = d_Wtab[cur_t * (H * H) + i * H + lane];

    int s0 = __shfl_sync(0xffffffffu, s, 0);
    float hv_next = d_h[s0 * H + lane];

#pragma unroll 1
    for (int j = 0; j < nb; j++) {
        float hv = hv_next;
        if (j + 1 < nb) {
            int sn = __shfl_sync(0xffffffffu, s, j + 1);
            hv_next = d_h[sn * H + lane];
        }
        int tj = __shfl_sync(0xffffffffu, t, j);
        if (tj != cur_t) {
            cur_t = tj;
#pragma unroll
            for (int i = 0; i < H; i++)
                w[i] = d_Wtab[cur_t * (H * H) + i * H + lane];
        }
        float a0 = 0.f, a1 = 0.f, a2 = 0.f, a3 = 0.f;
#pragma unroll
        for (int i = 0; i < H; i += 4) {
            a0 = fmaf(__shfl_sync(0xffffffffu, hv, i + 0), w[i + 0], a0);
            a1 = fmaf(__shfl_sync(0xffffffffu, hv, i + 1), w[i + 1], a1);
            a2 = fmaf(__shfl_sync(0xffffffffu, hv, i + 2), w[i + 2], a2);
            a3 = fmaf(__shfl_sync(0xffffffffu, hv, i + 3), w[i + 3], a3);
        }
        int dj = __shfl_sync(0xffffffffu, d, j);
        atomicAdd(&d_agg[dj * H + lane], (a0 + a1) + (a2 + a3));
    }
}

// ---------------- GRU kernel ----------------
__global__ void k_gru(const float* __restrict__ gWih,
                      const float* __restrict__ gWhh,
                      const float* __restrict__ gbih,
                      const float* __restrict__ gbhh,
                      const float* __restrict__ cb,
                      float* __restrict__ outp) {
    __shared__ __align__(16) float sWih[3 * H * H];
    __shared__ __align__(16) float sWhh[3 * H * H];
    __shared__ float sbih[3 * H], sbhh[3 * H], scb[H];

    for (int i = threadIdx.x; i < 3 * H * H; i += blockDim.x) {
        sWih[i] = gWih[i];
        sWhh[i] = gWhh[i];
    }
    for (int i = threadIdx.x; i < 3 * H; i += blockDim.x) {
        sbih[i] = gbih[i];
        sbhh[i] = gbhh[i];
    }
    if (threadIdx.x < H) scb[threadIdx.x] = cb[threadIdx.x];
    __syncthreads();

    int n = blockIdx.x * blockDim.x + threadIdx.x;
    if (n >= NN) return;

    unsigned long long m2[H / 2], h2[H / 2];
    {
        const float4* ag4 = (const float4*)(d_agg + (size_t)n * H);
        float4* agw = (float4*)(d_agg + (size_t)n * H);
        const float4* hh4 = (const float4*)(d_h + (size_t)n * H);
        float4 z4 = make_float4(0.f, 0.f, 0.f, 0.f);
#pragma unroll
        for (int q = 0; q < H / 4; q++) {
            float4 a = ag4[q];
            float b0 = fmaxf(a.x + scb[q * 4 + 0], 0.f);
            float b1 = fmaxf(a.y + scb[q * 4 + 1], 0.f);
            float b2 = fmaxf(a.z + scb[q * 4 + 2], 0.f);
            float b3 = fmaxf(a.w + scb[q * 4 + 3], 0.f);
            m2[2 * q + 0] = pk(b0, b1);
            m2[2 * q + 1] = pk(b2, b3);
            agw[q] = z4;
            float4 hh = hh4[q];
            h2[2 * q + 0] = pk(hh.x, hh.y);
            h2[2 * q + 1] = pk(hh.z, hh.w);
        }
    }

#pragma unroll 1
    for (int o = 0; o < H; o++) {
        const ulonglong2* Wr = (const ulonglong2*)(sWih + o * H);
        const ulonglong2* Wz = (const ulonglong2*)(sWih + (H + o) * H);
        const ulonglong2* Wn = (const ulonglong2*)(sWih + (2 * H + o) * H);
        const ulonglong2* Vr = (const ulonglong2*)(sWhh + o * H);
        const ulonglong2* Vz = (const ulonglong2*)(sWhh + (H + o) * H);
        const ulonglong2* Vn = (const ulonglong2*)(sWhh + (2 * H + o) * H);
        unsigned long long air = 0, aiz = 0, ain = 0, ahr = 0, ahz = 0, ahn = 0;
#pragma unroll
        for (int p = 0; p < H / 4; p++) {
            ulonglong2 w;
            w = Wr[p]; ffma2(air, m2[2 * p], w.x); ffma2(air, m2[2 * p + 1], w.y);
            w = Wz[p]; ffma2(aiz, m2[2 * p], w.x); ffma2(aiz, m2[2 * p + 1], w.y);
            w = Wn[p]; ffma2(ain, m2[2 * p], w.x); ffma2(ain, m2[2 * p + 1], w.y);
            w = Vr[p]; ffma2(ahr, h2[2 * p], w.x); ffma2(ahr, h2[2 * p + 1], w.y);
            w = Vz[p]; ffma2(ahz, h2[2 * p], w.x); ffma2(ahz, h2[2 * p + 1], w.y);
            w = Vn[p]; ffma2(ahn, h2[2 * p], w.x); ffma2(ahn, h2[2 * p + 1], w.y);
        }
        float2 f;
        f = upk(air); float ir = f.x + f.y + sbih[o];
        f = upk(aiz); float iz = f.x + f.y + sbih[H + o];
        f = upk(ain); float in_ = f.x + f.y + sbih[2 * H + o];
        f = upk(ahr); float hr = f.x + f.y + sbhh[o];
        f = upk(ahz); float hz = f.x + f.y + sbhh[H + o];
        f = upk(ahn); float hn = f.x + f.y + sbhh[2 * H + o];

        float r = sigm(ir + hr);
        float z = sigm(iz + hz);
        float nn = tanh_fast(in_ + r * hn);
        float2 hp = upk(h2[o >> 1]);
        float hdo = (o & 1) ? hp.y : hp.x;
        float hnew = (1.0f - z) * nn + z * hdo;
        d_h[(size_t)n * H + o] = hnew;
        if (outp) outp[(size_t)n * H + o] = hnew;
    }
}

// ---------------- launch ----------------
extern "C" void kernel_launch(void* const* d_in, const int* in_sizes, int n_in,
                              void* d_out, int out_size) {
    const int* node_ids = (const int*)d_in[0];
    const int* edge_ids = (const int*)d_in[1];
    const int* src = (const int*)d_in[2];
    const int* dst = (const int*)d_in[3];
    const float* node_emb = (const float*)d_in[4];
    const float* edge_emb = (const float*)d_in[5];
    const float* proj_W = (const float*)d_in[6];
    const float* proj_b = (const float*)d_in[7];
    const float* eW1 = (const float*)d_in[8];
    const float* eb1 = (const float*)d_in[9];
    const float* eW2 = (const float*)d_in[10];
    const float* eb2 = (const float*)d_in[11];
    const float* conv_bias = (const float*)d_in[12];
    const float* gWih = (const float*)d_in[13];
    const float* gWhh = (const float*)d_in[14];
    const float* gbih = (const float*)d_in[15];
    const float* gbhh = (const float*)d_in[16];
    float* out = (float*)d_out;

    k_zero_cnt<<<1, 32>>>();
    k_count<<<(NE + 255) / 256, 256>>>(edge_ids);
    k_scan<<<1, 1>>>();
    k_scatter<<<(NE + 255) / 256, 256>>>(edge_ids, src, dst);
    k_htab<<<NTN, H>>>(node_emb, proj_W, proj_b);
    k_wtab<<<dim3(NTE, (H * H) / EH), EH>>>(edge_emb, eW1, eb1, eW2, eb2);
    k_init<<<(NN * H + 255) / 256, 256>>>(node_ids);

    for (int s = 0; s < STEPS; s++) {
        k_message<<<MSG_BLOCKS, MSG_TPB>>>();
        float* op = (s == STEPS - 1) ? out : nullptr;
        k_gru<<<(NN + 255) / 256, 256>>>(gWih, gWhh, gbih, gbhh, conv_bias, op);
    }
}

// round 3
// speedup vs baseline: 1.2226x; 1.0582x over previous
#include <cuda_runtime.h>

#define NN 50000
#define NE 100000
#define NODE_IN 64
#define EDGE_IN 16
#define H 32
#define EH 128
#define NTN 343
#define NTE 21
#define STEPS 6

// ---------------- device scratch (no allocations allowed) ----------------
__device__ float d_h[NN * H];          // current hidden/h
__device__ float d_agg[NN * H];        // aggregated messages
__device__ float d_Wtab[NTE * H * H];  // per-type edge weight matrices
__device__ float d_htab[NTN * H];      // per-type projected node feats
__device__ int d_ssrc[NE];             // type-sorted edges
__device__ int d_sdst[NE];
__device__ int d_stype[NE];
__device__ int d_cnt[NTE];
__device__ int d_cur[NTE];

// ---------------- small helpers ----------------
__device__ __forceinline__ unsigned long long pk(float a, float b) {
    unsigned long long r;
    asm("mov.b64 %0, {%1, %2};" : "=l"(r) : "f"(a), "f"(b));
    return r;
}
__device__ __forceinline__ float2 upk(unsigned long long v) {
    float2 f;
    asm("mov.b64 {%0, %1}, %2;" : "=f"(f.x), "=f"(f.y) : "l"(v));
    return f;
}
__device__ __forceinline__ void ffma2(unsigned long long& acc,
                                      unsigned long long a,
                                      unsigned long long b) {
    asm("fma.rn.f32x2 %0, %1, %2, %0;" : "+l"(acc) : "l"(a), "l"(b));
}
__device__ __forceinline__ float sigm(float x) {
    return 1.0f / (1.0f + __expf(-x));
}
__device__ __forceinline__ float tanh_fast(float x) {
    float e = __expf(2.0f * x);
    return 1.0f - 2.0f / (e + 1.0f);
}

// ---------------- setup kernels ----------------
__global__ void k_zero_cnt() {
    int t = threadIdx.x;
    if (t < NTE) d_cnt[t] = 0;
}

__global__ void k_count(const int* __restrict__ eid) {
    __shared__ int hc[NTE];
    if (threadIdx.x < NTE) hc[threadIdx.x] = 0;
    __syncthreads();
    int e = blockIdx.x * blockDim.x + threadIdx.x;
    if (e < NE) atomicAdd(&hc[eid[e]], 1);
    __syncthreads();
    if (threadIdx.x < NTE && hc[threadIdx.x])
        atomicAdd(&d_cnt[threadIdx.x], hc[threadIdx.x]);
}

__global__ void k_scan() {
    int run = 0;
    for (int t = 0; t < NTE; t++) {
        d_cur[t] = run;
        run += d_cnt[t];
    }
}

__global__ void k_scatter(const int* __restrict__ eid,
                          const int* __restrict__ src,
                          const int* __restrict__ dst) {
    __shared__ int hc[NTE];
    __shared__ int hbase[NTE];
    if (threadIdx.x < NTE) hc[threadIdx.x] = 0;
    __syncthreads();
    int e = blockIdx.x * blockDim.x + threadIdx.x;
    int t = 0, loc = 0;
    bool valid = (e < NE);
    if (valid) {
        t = eid[e];
        loc = atomicAdd(&hc[t], 1);
    }
    __syncthreads();
    if (threadIdx.x < NTE && hc[threadIdx.x])
        hbase[threadIdx.x] = atomicAdd(&d_cur[threadIdx.x], hc[threadIdx.x]);
    __syncthreads();
    if (valid) {
        int p = hbase[t] + loc;
        d_ssrc[p] = src[e];
        d_sdst[p] = dst[e];
        d_stype[p] = t;
    }
}

__global__ void k_htab(const float* __restrict__ node_emb,
                       const float* __restrict__ proj_W,
                       const float* __restrict__ proj_b) {
    int r = blockIdx.x;
    int o = threadIdx.x;
    float acc = proj_b[o];
    for (int i = 0; i < NODE_IN; i++)
        acc = fmaf(node_emb[r * NODE_IN + i], proj_W[i * H + o], acc);
    d_htab[r * H + o] = fmaxf(acc, 0.0f);
}

__global__ void k_wtab(const float* __restrict__ edge_emb,
                       const float* __restrict__ eW1,
                       const float* __restrict__ eb1,
                       const float* __restrict__ eW2,
                       const float* __restrict__ eb2) {
    __shared__ float sh[EH];
    int t = blockIdx.x;
    int c = blockIdx.y;
    int k = threadIdx.x;
    float a = eb1[k];
#pragma unroll
    for (int i = 0; i < EDGE_IN; i++)
        a = fmaf(edge_emb[t * EDGE_IN + i], eW1[i * EH + k], a);
    sh[k] = fmaxf(a, 0.0f);
    __syncthreads();
    int o = c * EH + k;
    float acc = eb2[o];
#pragma unroll 8
    for (int i = 0; i < EH; i++)
        acc = fmaf(sh[i], eW2[i * (H * H) + o], acc);
    d_Wtab[t * (H * H) + o] = acc;
}

__global__ void k_init(const int* __restrict__ node_ids) {
    int idx = blockIdx.x * blockDim.x + threadIdx.x;
    if (idx < NN * H) {
        int n = idx >> 5, o = idx & 31;
        d_h[idx] = d_htab[node_ids[n] * H + o];
        d_agg[idx] = 0.0f;
    }
}

// ---------------- message kernel ----------------
// Two-phase per warp-chunk of 32 type-sorted edges:
//  Phase 1: gather the 32 h[src] rows into smem (32 independent coalesced
//           LDGs, MLP=32 -> L2 latency overlapped).
//  Phase 2: per edge, 8 LDS.128 broadcasts + 16 packed ffma2 into a 2-wide
//           accumulator; W register-resident as packed f32x2 pairs,
//           reloaded only at (rare) type boundaries.
#define MSG_TPB 256
#define MSG_WPB (MSG_TPB / 32)
#define MSG_NWARPS ((NE + 31) / 32)
#define MSG_BLOCKS ((MSG_NWARPS + MSG_WPB - 1) / MSG_WPB)

__global__ void __launch_bounds__(MSG_TPB) k_message() {
    __shared__ __align__(16) float hs[MSG_WPB][32][32];
    int wid = threadIdx.x >> 5;
    int lane = threadIdx.x & 31;
    int gw = blockIdx.x * MSG_WPB + wid;
    int base = gw * 32;
    if (base >= NE) return;
    int nb = min(32, NE - base);
    const unsigned FULL = 0xffffffffu;

    int s = 0, d = 0, t = 0;
    if (lane < nb) {
        int e = base + lane;
        s = __ldg(&d_ssrc[e]);
        d = __ldg(&d_sdst[e]);
        t = __ldg(&d_stype[e]);
    }

    // Phase 1: stage h rows (independent loads, deep MLP)
#pragma unroll 4
    for (int j = 0; j < nb; j++) {
        int sj = __shfl_sync(FULL, s, j);
        hs[wid][j][lane] = d_h[sj * H + lane];
    }

    // W packed into f32x2 pairs: w2[q] covers inputs (2q, 2q+1), output=lane
    int cur_t = __shfl_sync(FULL, t, 0);
    unsigned long long w2[H / 2];
    {
        const float* Wt = d_Wtab + cur_t * (H * H);
#pragma unroll
        for (int q = 0; q < H / 2; q++)
            w2[q] = pk(Wt[(2 * q) * H + lane], Wt[(2 * q + 1) * H + lane]);
    }
    __syncwarp();

    // Phase 2: compute + scatter
#pragma unroll 2
    for (int j = 0; j < nb; j++) {
        int tj = __shfl_sync(FULL, t, j);
        if (tj != cur_t) {
            cur_t = tj;
            const float* Wt = d_Wtab + cur_t * (H * H);
#pragma unroll
            for (int q = 0; q < H / 2; q++)
                w2[q] = pk(Wt[(2 * q) * H + lane], Wt[(2 * q + 1) * H + lane]);
        }
        const ulonglong2* hp = (const ulonglong2*)hs[wid][j];
        unsigned long long acc = 0;
#pragma unroll
        for (int p = 0; p < 8; p++) {
            ulonglong2 hh = hp[p];  // LDS.128 broadcast: h[4p..4p+3]
            ffma2(acc, hh.x, w2[2 * p]);
            ffma2(acc, hh.y, w2[2 * p + 1]);
        }
        float2 f = upk(acc);
        int dj = __shfl_sync(FULL, d, j);
        atomicAdd(&d_agg[dj * H + lane], f.x + f.y);
    }
}

// ---------------- GRU kernel ----------------
__global__ void k_gru(const float* __restrict__ gWih,
                      const float* __restrict__ gWhh,
                      const float* __restrict__ gbih,
                      const float* __restrict__ gbhh,
                      const float* __restrict__ cb,
                      float* __restrict__ outp) {
    __shared__ __align__(16) float sWih[3 * H * H];
    __shared__ __align__(16) float sWhh[3 * H * H];
    __shared__ float sbih[3 * H], sbhh[3 * H], scb[H];

    for (int i = threadIdx.x; i < 3 * H * H; i += blockDim.x) {
        sWih[i] = gWih[i];
        sWhh[i] = gWhh[i];
    }
    for (int i = threadIdx.x; i < 3 * H; i += blockDim.x) {
        sbih[i] = gbih[i];
        sbhh[i] = gbhh[i];
    }
    if (threadIdx.x < H) scb[threadIdx.x] = cb[threadIdx.x];
    __syncthreads();

    int n = blockIdx.x * blockDim.x + threadIdx.x;
    if (n >= NN) return;

    unsigned long long m2[H / 2], h2[H / 2];
    {
        const float4* ag4 = (const float4*)(d_agg + (size_t)n * H);
        float4* agw = (float4*)(d_agg + (size_t)n * H);
        const float4* hh4 = (const float4*)(d_h + (size_t)n * H);
        float4 z4 = make_float4(0.f, 0.f, 0.f, 0.f);
#pragma unroll
        for (int q = 0; q < H / 4; q++) {
            float4 a = ag4[q];
            float b0 = fmaxf(a.x + scb[q * 4 + 0], 0.f);
            float b1 = fmaxf(a.y + scb[q * 4 + 1], 0.f);
            float b2 = fmaxf(a.z + scb[q * 4 + 2], 0.f);
            float b3 = fmaxf(a.w + scb[q * 4 + 3], 0.f);
            m2[2 * q + 0] = pk(b0, b1);
            m2[2 * q + 1] = pk(b2, b3);
            agw[q] = z4;
            float4 hh = hh4[q];
            h2[2 * q + 0] = pk(hh.x, hh.y);
            h2[2 * q + 1] = pk(hh.z, hh.w);
        }
    }

#pragma unroll 1
    for (int o = 0; o < H; o++) {
        const ulonglong2* Wr = (const ulonglong2*)(sWih + o * H);
        const ulonglong2* Wz = (const ulonglong2*)(sWih + (H + o) * H);
        const ulonglong2* Wn = (const ulonglong2*)(sWih + (2 * H + o) * H);
        const ulonglong2* Vr = (const ulonglong2*)(sWhh + o * H);
        const ulonglong2* Vz = (const ulonglong2*)(sWhh + (H + o) * H);
        const ulonglong2* Vn = (const ulonglong2*)(sWhh + (2 * H + o) * H);
        unsigned long long air = 0, aiz = 0, ain = 0, ahr = 0, ahz = 0, ahn = 0;
#pragma unroll
        for (int p = 0; p < H / 4; p++) {
            ulonglong2 w;
            w = Wr[p]; ffma2(air, m2[2 * p], w.x); ffma2(air, m2[2 * p + 1], w.y);
            w = Wz[p]; ffma2(aiz, m2[2 * p], w.x); ffma2(aiz, m2[2 * p + 1], w.y);
            w = Wn[p]; ffma2(ain, m2[2 * p], w.x); ffma2(ain, m2[2 * p + 1], w.y);
            w = Vr[p]; ffma2(ahr, h2[2 * p], w.x); ffma2(ahr, h2[2 * p + 1], w.y);
            w = Vz[p]; ffma2(ahz, h2[2 * p], w.x); ffma2(ahz, h2[2 * p + 1], w.y);
            w = Vn[p]; ffma2(ahn, h2[2 * p], w.x); ffma2(ahn, h2[2 * p + 1], w.y);
        }
        float2 f;
        f = upk(air); float ir = f.x + f.y + sbih[o];
        f = upk(aiz); float iz = f.x + f.y + sbih[H + o];
        f = upk(ain); float in_ = f.x + f.y + sbih[2 * H + o];
        f = upk(ahr); float hr = f.x + f.y + sbhh[o];
        f = upk(ahz); float hz = f.x + f.y + sbhh[H + o];
        f = upk(ahn); float hn = f.x + f.y + sbhh[2 * H + o];

        float r = sigm(ir + hr);
        float z = sigm(iz + hz);
        float nn = tanh_fast(in_ + r * hn);
        float2 hp = upk(h2[o >> 1]);
        float hdo = (o & 1) ? hp.y : hp.x;
        float hnew = (1.0f - z) * nn + z * hdo;
        d_h[(size_t)n * H + o] = hnew;
        if (outp) outp[(size_t)n * H + o] = hnew;
    }
}

// ---------------- launch ----------------
extern "C" void kernel_launch(void* const* d_in, const int* in_sizes, int n_in,
                              void* d_out, int out_size) {
    const int* node_ids = (const int*)d_in[0];
    const int* edge_ids = (const int*)d_in[1];
    const int* src = (const int*)d_in[2];
    const int* dst = (const int*)d_in[3];
    const float* node_emb = (const float*)d_in[4];
    const float* edge_emb = (const float*)d_in[5];
    const float* proj_W = (const float*)d_in[6];
    const float* proj_b = (const float*)d_in[7];
    const float* eW1 = (const float*)d_in[8];
    const float* eb1 = (const float*)d_in[9];
    const float* eW2 = (const float*)d_in[10];
    const float* eb2 = (const float*)d_in[11];
    const float* conv_bias = (const float*)d_in[12];
    const float* gWih = (const float*)d_in[13];
    const float* gWhh = (const float*)d_in[14];
    const float* gbih = (const float*)d_in[15];
    const float* gbhh = (const float*)d_in[16];
    float* out = (float*)d_out;

    k_zero_cnt<<<1, 32>>>();
    k_count<<<(NE + 255) / 256, 256>>>(edge_ids);
    k_scan<<<1, 1>>>();
    k_scatter<<<(NE + 255) / 256, 256>>>(edge_ids, src, dst);
    k_htab<<<NTN, H>>>(node_emb, proj_W, proj_b);
    k_wtab<<<dim3(NTE, (H * H) / EH), EH>>>(edge_emb, eW1, eb1, eW2, eb2);
    k_init<<<(NN * H + 255) / 256, 256>>>(node_ids);

    for (int s = 0; s < STEPS; s++) {
        k_message<<<MSG_BLOCKS, MSG_TPB>>>();
        float* op = (s == STEPS - 1) ? out : nullptr;
        k_gru<<<(NN + 255) / 256, 256>>>(gWih, gWhh, gbih, gbhh, conv_bias, op);
    }
}